// round 3
// baseline (speedup 1.0000x reference)
#include <cuda_runtime.h>

#define TPB  256
#define ST   17            // padded row stride (float2 units)
#define SITE (32*ST)       // 544 float2 per site tensor

__device__ __forceinline__ void cmac(float2& acc, float2 a, float2 b) {        // acc += a*b
    acc.x = fmaf(a.x, b.x, fmaf(-a.y, b.y, acc.x));
    acc.y = fmaf(a.x, b.y, fmaf( a.y, b.x, acc.y));
}
__device__ __forceinline__ void cmacc(float2& acc, float2 a, float2 b) {       // acc += a*conj(b)
    acc.x = fmaf(a.x, b.x, fmaf( a.y, b.y, acc.x));
    acc.y = fmaf(a.y, b.x, fmaf(-a.x, b.y, acc.y));
}

// smem: bufA 18*544 | bufB 18*544 | Ush 72 | Msct 544 | Msc 512 | Renv 256 | Lenv 768 | red 64f
#define F2_TOTAL (2*18*SITE + 72 + SITE + 512 + 256 + 768)
#define SMEM_BYTES (F2_TOTAL*8 + 64*4)

// Renv <- sum_s A_j^s . Renv . A_j^s(dagger), chi=16.
// Phase 2 exploits Hermiticity: only 136 upper-triangle dots, mirror-write conj.
__device__ __forceinline__ void transfer(const float2* __restrict__ Aj,
                                         float2* __restrict__ Renv,
                                         float2* __restrict__ Msct,
                                         int t, int ta1, int ta2)
{
    // phase 1: M = A (32x16) . Renv (16x16); write conj-transposed, stride 17
    {
        const int r = t >> 4, bp = t & 15;
        const float2* row0 = Aj + r*ST;
        const float2* row1 = row0 + 16*ST;
        float2 acc0 = make_float2(0.f,0.f), acc1 = make_float2(0.f,0.f);
#pragma unroll
        for (int be = 0; be < 16; ++be) {
            float2 rv = Renv[be*16 + bp];
            cmac(acc0, row0[be], rv);
            cmac(acc1, row1[be], rv);
        }
        const int s = r & 1, al = r >> 1;
        const int k = s*16 + bp;
        Msct[k*ST + al    ] = make_float2(acc0.x, -acc0.y);
        Msct[k*ST + al + 8] = make_float2(acc1.x, -acc1.y);
    }
    __syncthreads();
    // phase 2 (Hermitian): P = sum_k A[a2][k]*Msct[k][a1]; Renv[a1][a2]=conj(P),
    // Renv[a2][a1]=P. Only a1<=a2 computed (136 threads).
    if (t < 136) {
        const float2* arow0 = Aj + (ta2*2)*ST;
        const float2* arow1 = arow0 + ST;
        float2 P0 = make_float2(0.f,0.f), P1 = make_float2(0.f,0.f);
#pragma unroll
        for (int c = 0; c < 16; ++c) {
            cmac(P0, arow0[c], Msct[c*ST + ta1]);
            cmac(P1, arow1[c], Msct[(16+c)*ST + ta1]);
        }
        const float px = P0.x + P1.x, py = P0.y + P1.y;
        Renv[ta1*16 + ta2] = make_float2(px, -py);
        if (ta1 != ta2) Renv[ta2*16 + ta1] = make_float2(px, py);
    }
    __syncthreads();
}

__global__ void __launch_bounds__(TPB, 1) vqc_mps_kernel(
    const float* __restrict__ w, const int* __restrict__ x, float* __restrict__ out)
{
    extern __shared__ float2 sm[];
    float2* bufA = sm;
    float2* bufB = bufA + 18*SITE;
    float2* Ush  = bufB + 18*SITE;
    float2* Msct = Ush + 72;
    float2* Msc  = Msct + SITE;
    float2* Renv = Msc + 512;
    float2* Lenv = Renv + 256;
    float*  red  = (float*)(Lenv + 768);

    const int b = blockIdx.x, t = threadIdx.x;
    const int lane = t & 31, wid = t >> 5;

    // triangle decode (for Hermitian phase 2), once into registers
    int ta1 = 0, trem = t;
    while (ta1 < 15 && trem >= 16 - ta1) { trem -= 16 - ta1; ++ta1; }
    const int ta2 = ta1 + trem;

    // product state |x_0..x_8, 0..0>  (no buffer zeroing needed: every read
    // region is written by the preceding layer; see analysis)
    if (t < 18) {
        int bit = (t < 9) ? x[b*9 + t] : 0;
        bufA[t*SITE + 0 ] = make_float2(bit == 0 ? 1.f : 0.f, 0.f);   // (al=0,s=0,be=0)
        bufA[t*SITE + ST] = make_float2(bit == 1 ? 1.f : 0.f, 0.f);   // (al=0,s=1,be=0)
    }
    __syncthreads();

    float2* A  = bufA;
    float2* Bb = bufB;

    // ---- 4 layers: fused (rotation + CNOT-staircase MPO), chi: c -> 2c ----
    for (int l = 0; l < 4; ++l) {
        const int c2 = 2 << l;
        const int cm = (1 << l) - 1;

        if (t < 18) {
            float phi = w[(l*18 + t)*3 + 0];
            float th  = w[(l*18 + t)*3 + 1];
            float om  = w[(l*18 + t)*3 + 2];
            float sh, ch; sincosf(0.5f*th, &sh, &ch);
            float sa, ca; sincosf(-0.5f*(phi + om), &sa, &ca);
            float sb, cb; sincosf( 0.5f*(phi - om), &sb, &cb);
            Ush[t*4+0] = make_float2( ca*ch,  sa*ch);
            Ush[t*4+1] = make_float2(-cb*sh, -sb*sh);
            Ush[t*4+2] = make_float2( cb*sh, -sb*sh);
            Ush[t*4+3] = make_float2( ca*ch, -sa*ch);
        }
        __syncthreads();

        for (int j = 0; j < 18; ++j) {
            const int Lo = (j == 0)  ? 1 : c2;
            const int Ro = (j == 17) ? 1 : c2;
            const int n  = Lo * 2 * Ro;
            const float2* Aj = A  + j*SITE;
            float2*       Bj = Bb + j*SITE;
            const float2 U00 = Ush[j*4+0], U01 = Ush[j*4+1];
            const float2 U10 = Ush[j*4+2], U11 = Ush[j*4+3];
            for (int i = t; i < n; i += TPB) {
                int bp, rest;
                if (j == 17) { bp = 0;           rest = i; }
                else         { bp = i & (c2-1);  rest = i >> (l+1); }
                const int s  = rest & 1;
                const int ap = rest >> 1;
                const int a  = (j == 0)  ? 0 : (ap >> l);
                const int al = (j == 0)  ? 0 : (ap & cm);
                const int kb = (j == 17) ? s : (bp >> l);
                const int be = (j == 17) ? 0 : (bp & cm);
                float2 v = make_float2(0.f, 0.f);
                if (kb == s) {
                    const int u = s ^ a;
                    float2 A0 = Aj[al*(2*ST) + be];
                    float2 A1 = Aj[al*(2*ST) + ST + be];
                    float2 Ua = (u == 0) ? U00 : U10;
                    float2 Ub = (u == 0) ? U01 : U11;
                    cmac(v, Ua, A0);
                    cmac(v, Ub, A1);
                }
                Bj[(ap*2 + s)*ST + bp] = v;
            }
        }
        __syncthreads();
        float2* tmp = A; A = Bb; Bb = tmp;
    }

    // ---- contraction, chi=16 everywhere ----

    // Renv init from site 17 (right dim 1): Hermitian Gram matrix
    {
        const int a1 = t >> 4, a2 = t & 15;
        const float2* A17 = A + 17*SITE;
        float2 acc = make_float2(0.f,0.f);
        cmacc(acc, A17[(a1*2  )*ST], A17[(a2*2  )*ST]);
        cmacc(acc, A17[(a1*2+1)*ST], A17[(a2*2+1)*ST]);
        Renv[a1*16 + a2] = acc;
    }
    __syncthreads();

    for (int j = 16; j >= 4; --j) transfer(A + j*SITE, Renv, Msct, t, ta1, ta2);

    // left environments L0,L1,L2
    {
        const int b1 = t >> 4, b2 = t & 15;
        const float2* A0 = A;
        float2 acc = make_float2(0.f,0.f);
        cmacc(acc, A0[b1],      A0[b2]);
        cmacc(acc, A0[ST + b1], A0[ST + b2]);
        Lenv[t] = acc;
    }
    __syncthreads();
    for (int m = 1; m <= 2; ++m) {
        const float2* Lp = Lenv + (m-1)*256;
        float2*       Ln = Lenv + m*256;
        const float2* Am = A + m*SITE;
        {
            const int g = t & 15, s = (t >> 4) & 1, b2a = t >> 5;
            float2 acc0 = make_float2(0.f,0.f), acc1 = make_float2(0.f,0.f);
#pragma unroll
            for (int b1 = 0; b1 < 16; ++b1) {
                float2 av = Am[(b1*2 + s)*ST + g];
                cmac(acc0, Lp[b1*16 + b2a    ], av);
                cmac(acc1, Lp[b1*16 + b2a + 8], av);
            }
            Msc[ b2a     *32 + s*16 + g] = acc0;
            Msc[(b2a + 8)*32 + s*16 + g] = acc1;
        }
        __syncthreads();
        {
            const int g1 = t >> 4, g2 = t & 15;
            float2 acc = make_float2(0.f,0.f);
#pragma unroll
            for (int kk = 0; kk < 32; ++kk)
                cmacc(acc, Msc[(kk>>1)*32 + (kk&1)*16 + g1], Am[kk*ST + g2]);
            Ln[t] = acc;
        }
        __syncthreads();
    }

    // ---- EVs q=3..0 ----
    for (int q = 3; q >= 0; --q) {
        const float2* Aq = A + q*SITE;

        // phase A: X[(al,s)][bp] = sum_be Aq[(al,s)][be] * Renv[be][bp]
        {
            const int r = t >> 4, bp = t & 15;
            const float2* row0 = Aq + r*ST;
            const float2* row1 = row0 + 16*ST;
            float2 acc0 = make_float2(0.f,0.f), acc1 = make_float2(0.f,0.f);
#pragma unroll
            for (int be = 0; be < 16; ++be) {
                float2 rv = Renv[be*16 + bp];
                cmac(acc0, row0[be], rv);
                cmac(acc1, row1[be], rv);
            }
            Msc[ r     *16 + bp] = acc0;
            Msc[(r+16) *16 + bp] = acc1;
        }
        __syncthreads();

        // phase B: signed contributions + two-level reduction
        float num = 0.f, den = 0.f;
        if (q == 0) {
            if (t < 32) {
                const int s = t >> 4, bp = t & 15;
                float2 z  = Msc[s*16 + bp];
                float2 av = Aq[s*ST + bp];
                float v = z.x*av.x + z.y*av.y;
                num = s ? -v : v;  den = v;
            }
        } else {
            const float2* Lp = Lenv + (q-1)*256;
            const int bp = t & 15, s = (t >> 4) & 1, a2a = t >> 5;
#pragma unroll
            for (int h = 0; h < 2; ++h) {
                const int a2 = a2a + h*8;
                float2 z = make_float2(0.f,0.f);
#pragma unroll
                for (int al = 0; al < 16; ++al)
                    cmac(z, Lp[al*16 + a2], Msc[(al*2 + s)*16 + bp]);
                float2 av = Aq[(a2*2 + s)*ST + bp];
                float v = z.x*av.x + z.y*av.y;
                num += s ? -v : v;  den += v;
            }
        }
#pragma unroll
        for (int o = 16; o > 0; o >>= 1) {
            num += __shfl_xor_sync(0xffffffffu, num, o);
            den += __shfl_xor_sync(0xffffffffu, den, o);
        }
        if (lane == 0) { red[wid*2] = num; red[wid*2+1] = den; }
        __syncthreads();
        if (t == 0) {
            float N = 0.f, D = 0.f;
#pragma unroll
            for (int wdx = 0; wdx < 8; ++wdx) { N += red[wdx*2]; D += red[wdx*2+1]; }
            out[b*4 + q] = N / D;
        }
        if (q > 0) transfer(Aq, Renv, Msct, t, ta1, ta2);
    }
}

extern "C" void kernel_launch(void* const* d_in, const int* in_sizes, int n_in,
                              void* d_out, int out_size) {
    const float* w;
    const int*   xin;
    if (n_in >= 2 && in_sizes[0] == 4*18*3) {
        w   = (const float*)d_in[0];
        xin = (const int*)  d_in[1];
    } else {
        w   = (const float*)d_in[1];
        xin = (const int*)  d_in[0];
    }
    float* out = (float*)d_out;

    cudaFuncSetAttribute(vqc_mps_kernel,
                         cudaFuncAttributeMaxDynamicSharedMemorySize,
                         (int)SMEM_BYTES);
    vqc_mps_kernel<<<64, TPB, SMEM_BYTES>>>(w, xin, out);
}